// round 2
// baseline (speedup 1.0000x reference)
#include <cuda_runtime.h>

#define BB 4
#define CC 128
#define NN 4096
#define OC 256
#define KNN 10

// Scratch (device globals — no allocation in kernel_launch)
static __device__ float g_score[(size_t)BB * NN * NN];   // 268 MB
static __device__ float g_xx[BB * NN];
static __device__ float g_xT[(size_t)BB * NN * CC];      // x transposed [b][n][c]
static __device__ float g_mT[(size_t)BB * NN * CC];      // neighbor mean [b][n][c]
static __device__ int   g_idx[BB * NN * KNN];
static __device__ float g_Wcat[OC * 2 * CC];

// ---------------------------------------------------------------------------
// K1a: per-point squared norm  xx[b][n] = sum_c x[b][c][n]^2
__global__ void xx_kernel(const float* __restrict__ x) {
    int b = blockIdx.y;
    int n = blockIdx.x * blockDim.x + threadIdx.x;
    const float* xb = x + (size_t)b * CC * NN;
    float s = 0.f;
#pragma unroll 8
    for (int c = 0; c < CC; c++) {
        float v = xb[(size_t)c * NN + n];
        s += v * v;
    }
    g_xx[b * NN + n] = s;
}

// ---------------------------------------------------------------------------
// K1b: transpose x[b][c][n] -> xT[b][n][c] (for coalesced neighbor gathers)
__global__ void transpose_kernel(const float* __restrict__ x) {
    __shared__ float tile[32][33];
    int b  = blockIdx.z;
    int c0 = blockIdx.y * 32;
    int n0 = blockIdx.x * 32;
    const float* xb = x + (size_t)b * CC * NN;
    int tx = threadIdx.x, ty = threadIdx.y;  // (32, 8)
#pragma unroll
    for (int r = 0; r < 32; r += 8)
        tile[ty + r][tx] = xb[(size_t)(c0 + ty + r) * NN + n0 + tx];
    __syncthreads();
#pragma unroll
    for (int r = 0; r < 32; r += 8)
        g_xT[((size_t)b * NN + n0 + ty + r) * CC + c0 + tx] = tile[tx][ty + r];
}

// ---------------------------------------------------------------------------
// K2: Gram + score epilogue.  score[b][n][m] = 2 * <x_n, x_m> - xx[m]
// 128x128 tile, 256 threads, 8x8 per thread.
__global__ void __launch_bounds__(256) gram_kernel(const float* __restrict__ x) {
    int b  = blockIdx.z;
    int n0 = blockIdx.y * 128;
    int m0 = blockIdx.x * 128;
    const float* xb = x + (size_t)b * CC * NN;

    __shared__ float As[8][128];
    __shared__ float Bs[8][128];

    int tid = threadIdx.x;
    int tx = tid % 16, ty = tid / 16;

    float acc[8][8];
#pragma unroll
    for (int i = 0; i < 8; i++)
#pragma unroll
        for (int j = 0; j < 8; j++) acc[i][j] = 0.f;

    for (int c0 = 0; c0 < CC; c0 += 8) {
#pragma unroll
        for (int l = 0; l < 4; l++) {
            int e   = tid + l * 256;
            int kk  = e / 128;
            int col = e % 128;
            As[kk][col] = xb[(size_t)(c0 + kk) * NN + n0 + col];
            Bs[kk][col] = xb[(size_t)(c0 + kk) * NN + m0 + col];
        }
        __syncthreads();
#pragma unroll
        for (int kk = 0; kk < 8; kk++) {
            float a[8], bf[8];
            float4 a0 = *(const float4*)&As[kk][ty * 8];
            float4 a1 = *(const float4*)&As[kk][ty * 8 + 4];
            float4 b0 = *(const float4*)&Bs[kk][tx * 8];
            float4 b1 = *(const float4*)&Bs[kk][tx * 8 + 4];
            a[0]=a0.x; a[1]=a0.y; a[2]=a0.z; a[3]=a0.w;
            a[4]=a1.x; a[5]=a1.y; a[6]=a1.z; a[7]=a1.w;
            bf[0]=b0.x; bf[1]=b0.y; bf[2]=b0.z; bf[3]=b0.w;
            bf[4]=b1.x; bf[5]=b1.y; bf[6]=b1.z; bf[7]=b1.w;
#pragma unroll
            for (int i = 0; i < 8; i++)
#pragma unroll
                for (int j = 0; j < 8; j++)
                    acc[i][j] += a[i] * bf[j];
        }
        __syncthreads();
    }

#pragma unroll
    for (int i = 0; i < 8; i++) {
        int n = n0 + ty * 8 + i;
        float* row = g_score + ((size_t)b * NN + n) * NN;
#pragma unroll
        for (int j = 0; j < 8; j++) {
            int m = m0 + tx * 8 + j;
            row[m] = 2.f * acc[i][j] - g_xx[b * NN + m];
        }
    }
}

// ---------------------------------------------------------------------------
// K3: top-K per row via 10x block argmax (tie-break: lowest index, like jax)
__global__ void __launch_bounds__(256) topk_kernel() {
    int b = blockIdx.y;
    int n = blockIdx.x;
    __shared__ float sv[NN];
    __shared__ float rv[256];
    __shared__ int   ri[256];
    const float* row = g_score + ((size_t)b * NN + n) * NN;
    int t = threadIdx.x;
    for (int i = t; i < NN; i += 256) sv[i] = row[i];
    __syncthreads();

    const float NEG_INF = __int_as_float(0xff800000);
    for (int k = 0; k < KNN; k++) {
        float best = NEG_INF;
        int   bi   = 0x7fffffff;
        for (int i = t; i < NN; i += 256) {
            float v = sv[i];
            if (v > best) { best = v; bi = i; }
        }
        rv[t] = best; ri[t] = bi;
        __syncthreads();
        for (int s = 128; s > 0; s >>= 1) {
            if (t < s) {
                float v2 = rv[t + s]; int i2 = ri[t + s];
                if (v2 > rv[t] || (v2 == rv[t] && i2 < ri[t])) { rv[t] = v2; ri[t] = i2; }
            }
            __syncthreads();
        }
        if (t == 0) {
            g_idx[(b * NN + n) * KNN + k] = ri[0];
            sv[ri[0]] = NEG_INF;
        }
        __syncthreads();
    }
}

// ---------------------------------------------------------------------------
// K4: neighbor mean  mT[b][n][c] = (1/K) sum_k xT[b][idx_k][c]
__global__ void gather_kernel() {
    int b = blockIdx.y;
    int n = blockIdx.x;
    int c = threadIdx.x;  // 128
    __shared__ int sidx[KNN];
    if (c < KNN) sidx[c] = g_idx[(b * NN + n) * KNN + c];
    __syncthreads();
    float acc = 0.f;
#pragma unroll
    for (int k = 0; k < KNN; k++)
        acc += g_xT[((size_t)b * NN + sidx[k]) * CC + c];
    g_mT[((size_t)b * NN + n) * CC + c] = acc / (float)KNN;
}

// ---------------------------------------------------------------------------
// K5: Wcat[o][c] = W1 for c<128, (W2 - W1) for c>=128
__global__ void wcat_kernel(const float* __restrict__ W) {
    int idx = blockIdx.x * 256 + threadIdx.x;  // 0 .. 65535
    int c = idx % (2 * CC);
    float v = W[idx];
    if (c >= CC) v -= W[idx - CC];
    g_Wcat[idx] = v;
}

// ---------------------------------------------------------------------------
// K6: out[b][o][n] = sum_c Wcat[o][c] * cat[c][n] + bias[o]
//     cat[0:128][n] = mT[b][n][c],  cat[128:256][n] = x[b][c][n]
__global__ void __launch_bounds__(256) out_gemm_kernel(
    const float* __restrict__ x, const float* __restrict__ bias,
    float* __restrict__ out) {
    int b  = blockIdx.z;
    int o0 = blockIdx.y * 128;
    int n0 = blockIdx.x * 128;
    const float* xb = x + (size_t)b * CC * NN;

    __shared__ float As[8][128];
    __shared__ float Bs[8][128];

    int tid = threadIdx.x;
    int tx = tid % 16, ty = tid / 16;

    float acc[8][8];
#pragma unroll
    for (int i = 0; i < 8; i++)
#pragma unroll
        for (int j = 0; j < 8; j++) acc[i][j] = 0.f;

    for (int c0 = 0; c0 < 2 * CC; c0 += 8) {
#pragma unroll
        for (int l = 0; l < 4; l++) {
            int e  = tid + l * 256;
            int kk = e % 8;
            int i  = e / 8;
            As[kk][i] = g_Wcat[(o0 + i) * (2 * CC) + c0 + kk];
        }
        if (c0 < CC) {
#pragma unroll
            for (int l = 0; l < 4; l++) {
                int e  = tid + l * 256;
                int kk = e % 8;
                int j  = e / 8;
                Bs[kk][j] = g_mT[((size_t)b * NN + n0 + j) * CC + c0 + kk];
            }
        } else {
#pragma unroll
            for (int l = 0; l < 4; l++) {
                int e  = tid + l * 256;
                int kk = e / 128;
                int j  = e % 128;
                Bs[kk][j] = xb[(size_t)(c0 - CC + kk) * NN + n0 + j];
            }
        }
        __syncthreads();
#pragma unroll
        for (int kk = 0; kk < 8; kk++) {
            float a[8], bf[8];
            float4 a0 = *(const float4*)&As[kk][ty * 8];
            float4 a1 = *(const float4*)&As[kk][ty * 8 + 4];
            float4 b0 = *(const float4*)&Bs[kk][tx * 8];
            float4 b1 = *(const float4*)&Bs[kk][tx * 8 + 4];
            a[0]=a0.x; a[1]=a0.y; a[2]=a0.z; a[3]=a0.w;
            a[4]=a1.x; a[5]=a1.y; a[6]=a1.z; a[7]=a1.w;
            bf[0]=b0.x; bf[1]=b0.y; bf[2]=b0.z; bf[3]=b0.w;
            bf[4]=b1.x; bf[5]=b1.y; bf[6]=b1.z; bf[7]=b1.w;
#pragma unroll
            for (int i = 0; i < 8; i++)
#pragma unroll
                for (int j = 0; j < 8; j++)
                    acc[i][j] += a[i] * bf[j];
        }
        __syncthreads();
    }

#pragma unroll
    for (int i = 0; i < 8; i++) {
        int o = o0 + ty * 8 + i;
        float bv = bias[o];
        float* orow = out + ((size_t)(b * OC + o)) * NN + n0 + tx * 8;
#pragma unroll
        for (int j = 0; j < 8; j++)
            orow[j] = acc[i][j] + bv;
    }
}

// ---------------------------------------------------------------------------
extern "C" void kernel_launch(void* const* d_in, const int* in_sizes, int n_in,
                              void* d_out, int out_size) {
    const float* x    = (const float*)d_in[0];
    const float* W    = (const float*)d_in[1];
    const float* bias = (const float*)d_in[2];
    float* out = (float*)d_out;

    xx_kernel<<<dim3(NN / 256, BB), 256>>>(x);
    transpose_kernel<<<dim3(NN / 32, CC / 32, BB), dim3(32, 8)>>>(x);
    gram_kernel<<<dim3(NN / 128, NN / 128, BB), 256>>>(x);
    topk_kernel<<<dim3(NN, BB), 256>>>();
    gather_kernel<<<dim3(NN, BB), 128>>>();
    wcat_kernel<<<OC, 256>>>(W);
    out_gemm_kernel<<<dim3(NN / 128, OC / 128, BB), 256>>>(x, bias, out);
}

// round 3
// speedup vs baseline: 1.6425x; 1.6425x over previous
#include <cuda_runtime.h>

#define BB 4
#define CC 128
#define NN 4096
#define OC 256
#define KNN 10

// Scratch (device globals — no allocation in kernel_launch)
static __device__ float g_score[(size_t)BB * NN * NN];   // 268 MB
static __device__ float g_xx[BB * NN];
static __device__ float g_xT[(size_t)BB * NN * CC];      // x transposed [b][n][c]
static __device__ float g_mT[(size_t)BB * NN * CC];      // neighbor mean [b][n][c]
static __device__ int   g_idx[BB * NN * KNN];
static __device__ float g_Wcat[OC * 2 * CC];

// ---------------------------------------------------------------------------
// K1a: per-point squared norm  xx[b][n] = sum_c x[b][c][n]^2
__global__ void xx_kernel(const float* __restrict__ x) {
    int b = blockIdx.y;
    int n = blockIdx.x * blockDim.x + threadIdx.x;
    const float* xb = x + (size_t)b * CC * NN;
    float s = 0.f;
#pragma unroll 8
    for (int c = 0; c < CC; c++) {
        float v = xb[(size_t)c * NN + n];
        s += v * v;
    }
    g_xx[b * NN + n] = s;
}

// ---------------------------------------------------------------------------
// K1b: transpose x[b][c][n] -> xT[b][n][c]
__global__ void transpose_kernel(const float* __restrict__ x) {
    __shared__ float tile[32][33];
    int b  = blockIdx.z;
    int c0 = blockIdx.y * 32;
    int n0 = blockIdx.x * 32;
    const float* xb = x + (size_t)b * CC * NN;
    int tx = threadIdx.x, ty = threadIdx.y;  // (32, 8)
#pragma unroll
    for (int r = 0; r < 32; r += 8)
        tile[ty + r][tx] = xb[(size_t)(c0 + ty + r) * NN + n0 + tx];
    __syncthreads();
#pragma unroll
    for (int r = 0; r < 32; r += 8)
        g_xT[((size_t)b * NN + n0 + ty + r) * CC + c0 + tx] = tile[tx][ty + r];
}

// ---------------------------------------------------------------------------
// K2: symmetric Gram + score epilogue.
// score[b][n][m] = 2 * <x_n, x_m> - xx[m].  Gram is symmetric, so only
// upper-triangle 128x128 tiles (ti <= tj) are computed; off-diagonal tiles
// are mirrored via an smem-staged transpose.
// 256 threads, 8x8 per thread, BK=8, double-buffered smem.
#define GRAM_SMEM_BYTES (128 * 129 * 4)  // stage (aliases pipeline buffers)

__global__ void __launch_bounds__(256) gram_kernel(const float* __restrict__ x) {
    extern __shared__ float sm[];
    float* As = sm;              // [2][8][128]
    float* Bs = sm + 2 * 8 * 128;
    float* stage = sm;           // [128][129], reused after compute

    int b = blockIdx.y;
    int t = blockIdx.x;
    // decode upper-tri tile id -> (ti, tj), ti <= tj, row ti has 32-ti tiles
    int ti = 0;
    while ((ti + 1) * 32 - (ti + 1) * ti / 2 <= t) ti++;
    int tj = ti + (t - (ti * 32 - ti * (ti - 1) / 2));
    int n0 = ti * 128, m0 = tj * 128;

    const float* xb = x + (size_t)b * CC * NN;
    int tid = threadIdx.x;
    int tx = tid % 16, ty = tid / 16;

    float acc[8][8];
#pragma unroll
    for (int i = 0; i < 8; i++)
#pragma unroll
        for (int j = 0; j < 8; j++) acc[i][j] = 0.f;

    // preload k-stage 0 into buffer 0
#pragma unroll
    for (int l = 0; l < 4; l++) {
        int e = tid + l * 256;
        int kk = e >> 7, col = e & 127;
        As[e] = xb[(size_t)kk * NN + n0 + col];
        Bs[e] = xb[(size_t)kk * NN + m0 + col];
    }
    __syncthreads();

    int buf = 0;
    for (int c0 = 0; c0 < CC; c0 += 8) {
        int nc = c0 + 8;
        float ra[4], rb[4];
        if (nc < CC) {
#pragma unroll
            for (int l = 0; l < 4; l++) {
                int e = tid + l * 256;
                int kk = e >> 7, col = e & 127;
                ra[l] = xb[(size_t)(nc + kk) * NN + n0 + col];
                rb[l] = xb[(size_t)(nc + kk) * NN + m0 + col];
            }
        }
#pragma unroll
        for (int kk = 0; kk < 8; kk++) {
            const float* ab = As + buf * 1024 + kk * 128;
            const float* bb = Bs + buf * 1024 + kk * 128;
            float a[8], bf[8];
            float4 a0 = *(const float4*)(ab + ty * 8);
            float4 a1 = *(const float4*)(ab + ty * 8 + 4);
            float4 b0 = *(const float4*)(bb + tx * 8);
            float4 b1 = *(const float4*)(bb + tx * 8 + 4);
            a[0]=a0.x; a[1]=a0.y; a[2]=a0.z; a[3]=a0.w;
            a[4]=a1.x; a[5]=a1.y; a[6]=a1.z; a[7]=a1.w;
            bf[0]=b0.x; bf[1]=b0.y; bf[2]=b0.z; bf[3]=b0.w;
            bf[4]=b1.x; bf[5]=b1.y; bf[6]=b1.z; bf[7]=b1.w;
#pragma unroll
            for (int i = 0; i < 8; i++)
#pragma unroll
                for (int j = 0; j < 8; j++)
                    acc[i][j] += a[i] * bf[j];
        }
        if (nc < CC) {
            int ob = buf ^ 1;
#pragma unroll
            for (int l = 0; l < 4; l++) {
                int e = tid + l * 256;
                As[ob * 1024 + e] = ra[l];
                Bs[ob * 1024 + e] = rb[l];
            }
            __syncthreads();
            buf = ob;
        }
    }

    // direct tile: score[n][m] = 2*acc - xx[m]
    float xxm[8];
#pragma unroll
    for (int j = 0; j < 8; j++) xxm[j] = g_xx[b * NN + m0 + tx * 8 + j];
#pragma unroll
    for (int i = 0; i < 8; i++) {
        int n = n0 + ty * 8 + i;
        float v[8];
#pragma unroll
        for (int j = 0; j < 8; j++) v[j] = 2.f * acc[i][j] - xxm[j];
        float* row = g_score + ((size_t)b * NN + n) * NN + m0 + tx * 8;
        ((float4*)row)[0] = make_float4(v[0], v[1], v[2], v[3]);
        ((float4*)row)[1] = make_float4(v[4], v[5], v[6], v[7]);
    }

    // mirror tile: score[m][n] = 2*acc - xx[n], via smem transpose
    if (ti != tj) {
        __syncthreads();  // everyone done with As/Bs (stage aliases them)
        float xxn[8];
#pragma unroll
        for (int i = 0; i < 8; i++) xxn[i] = g_xx[b * NN + n0 + ty * 8 + i];
#pragma unroll
        for (int i = 0; i < 8; i++)
#pragma unroll
            for (int j = 0; j < 8; j++)
                stage[(tx * 8 + j) * 129 + ty * 8 + i] = 2.f * acc[i][j] - xxn[i];
        __syncthreads();
        int r  = tid >> 1;           // 0..127 : local m
        int ch = (tid & 1) * 64;     // column half
        float* row = g_score + ((size_t)b * NN + m0 + r) * NN + n0 + ch;
        const float* srow = stage + r * 129 + ch;
#pragma unroll
        for (int q = 0; q < 16; q++) {
            ((float4*)row)[q] = make_float4(srow[q * 4 + 0], srow[q * 4 + 1],
                                            srow[q * 4 + 2], srow[q * 4 + 3]);
        }
    }
}

// ---------------------------------------------------------------------------
// K3: top-K per row, one warp per row.
// Per-lane register-resident sorted top-10 over 128 strided elements,
// then 10-round warp-shuffle merge. Tie-break: value desc, index asc (jax).
#define TK_INSERT(v, idx)                                                    \
    do {                                                                     \
        float _v = (v);                                                      \
        if (_v > lv[KNN - 1]) {                                              \
            float cv = _v; int ci = (idx);                                   \
            _Pragma("unroll")                                                \
            for (int k = 0; k < KNN; k++) {                                  \
                if (cv > lv[k]) {                                            \
                    float tv = lv[k]; lv[k] = cv; cv = tv;                   \
                    int   tq = li[k]; li[k] = ci; ci = tq;                   \
                }                                                            \
            }                                                                \
        }                                                                    \
    } while (0)

__global__ void __launch_bounds__(256) topk_kernel() {
    int gw   = (blockIdx.x * 256 + threadIdx.x) >> 5;  // global row
    int lane = threadIdx.x & 31;
    int b = gw >> 12;        // / NN
    int n = gw & (NN - 1);
    const float4* row = (const float4*)(g_score + ((size_t)b * NN + n) * NN);

    const float NEG = -3.4028235e38f;
    float lv[KNN];
    int   li[KNN];
#pragma unroll
    for (int k = 0; k < KNN; k++) { lv[k] = NEG; li[k] = 0x7fffffff; }

#pragma unroll 4
    for (int j = 0; j < NN / 4 / 32; j++) {  // 32 iterations
        float4 v = row[j * 32 + lane];
        int base = (j * 32 + lane) * 4;
        TK_INSERT(v.x, base + 0);
        TK_INSERT(v.y, base + 1);
        TK_INSERT(v.z, base + 2);
        TK_INSERT(v.w, base + 3);
    }

#pragma unroll
    for (int r = 0; r < KNN; r++) {
        float cv = lv[0]; int ci = li[0];
        float bv = cv;    int bi = ci;
#pragma unroll
        for (int off = 16; off; off >>= 1) {
            float ov = __shfl_xor_sync(0xffffffffu, bv, off);
            int   oi = __shfl_xor_sync(0xffffffffu, bi, off);
            if (ov > bv || (ov == bv && oi < bi)) { bv = ov; bi = oi; }
        }
        if (lane == r) g_idx[(b * NN + n) * KNN + r] = bi;
        if (bi == ci) {  // this lane won (global indices unique): pop head
#pragma unroll
            for (int k = 0; k < KNN - 1; k++) { lv[k] = lv[k + 1]; li[k] = li[k + 1]; }
            lv[KNN - 1] = NEG; li[KNN - 1] = 0x7fffffff;
        }
    }
}

// ---------------------------------------------------------------------------
// K4: neighbor mean  mT[b][n][c] = (1/K) sum_k xT[b][idx_k][c]
__global__ void gather_kernel() {
    int b = blockIdx.y;
    int n = blockIdx.x;
    int c = threadIdx.x;  // 128
    __shared__ int sidx[KNN];
    if (c < KNN) sidx[c] = g_idx[(b * NN + n) * KNN + c];
    __syncthreads();
    float acc = 0.f;
#pragma unroll
    for (int k = 0; k < KNN; k++)
        acc += g_xT[((size_t)b * NN + sidx[k]) * CC + c];
    g_mT[((size_t)b * NN + n) * CC + c] = acc / (float)KNN;
}

// ---------------------------------------------------------------------------
// K5: Wcat[o][c] = W1 for c<128, (W2 - W1) for c>=128
__global__ void wcat_kernel(const float* __restrict__ W) {
    int idx = blockIdx.x * 256 + threadIdx.x;
    int c = idx % (2 * CC);
    float v = W[idx];
    if (c >= CC) v -= W[idx - CC];
    g_Wcat[idx] = v;
}

// ---------------------------------------------------------------------------
// K6: out[b][o][n] = sum_c Wcat[o][c] * cat[c][n] + bias[o]
__global__ void __launch_bounds__(256) out_gemm_kernel(
    const float* __restrict__ x, const float* __restrict__ bias,
    float* __restrict__ out) {
    int b  = blockIdx.z;
    int o0 = blockIdx.y * 128;
    int n0 = blockIdx.x * 128;
    const float* xb = x + (size_t)b * CC * NN;

    __shared__ float As[8][128];
    __shared__ float Bs[8][128];

    int tid = threadIdx.x;
    int tx = tid % 16, ty = tid / 16;

    float acc[8][8];
#pragma unroll
    for (int i = 0; i < 8; i++)
#pragma unroll
        for (int j = 0; j < 8; j++) acc[i][j] = 0.f;

    for (int c0 = 0; c0 < 2 * CC; c0 += 8) {
#pragma unroll
        for (int l = 0; l < 4; l++) {
            int e  = tid + l * 256;
            int kk = e % 8;
            int i  = e / 8;
            As[kk][i] = g_Wcat[(o0 + i) * (2 * CC) + c0 + kk];
        }
        if (c0 < CC) {
#pragma unroll
            for (int l = 0; l < 4; l++) {
                int e  = tid + l * 256;
                int kk = e % 8;
                int j  = e / 8;
                Bs[kk][j] = g_mT[((size_t)b * NN + n0 + j) * CC + c0 + kk];
            }
        } else {
#pragma unroll
            for (int l = 0; l < 4; l++) {
                int e  = tid + l * 256;
                int kk = e / 128;
                int j  = e % 128;
                Bs[kk][j] = xb[(size_t)(c0 - CC + kk) * NN + n0 + j];
            }
        }
        __syncthreads();
#pragma unroll
        for (int kk = 0; kk < 8; kk++) {
            float a[8], bf[8];
            float4 a0 = *(const float4*)&As[kk][ty * 8];
            float4 a1 = *(const float4*)&As[kk][ty * 8 + 4];
            float4 b0 = *(const float4*)&Bs[kk][tx * 8];
            float4 b1 = *(const float4*)&Bs[kk][tx * 8 + 4];
            a[0]=a0.x; a[1]=a0.y; a[2]=a0.z; a[3]=a0.w;
            a[4]=a1.x; a[5]=a1.y; a[6]=a1.z; a[7]=a1.w;
            bf[0]=b0.x; bf[1]=b0.y; bf[2]=b0.z; bf[3]=b0.w;
            bf[4]=b1.x; bf[5]=b1.y; bf[6]=b1.z; bf[7]=b1.w;
#pragma unroll
            for (int i = 0; i < 8; i++)
#pragma unroll
                for (int j = 0; j < 8; j++)
                    acc[i][j] += a[i] * bf[j];
        }
        __syncthreads();
    }

#pragma unroll
    for (int i = 0; i < 8; i++) {
        int o = o0 + ty * 8 + i;
        float bv = bias[o];
        float* orow = out + ((size_t)(b * OC + o)) * NN + n0 + tx * 8;
#pragma unroll
        for (int j = 0; j < 8; j++)
            orow[j] = acc[i][j] + bv;
    }
}

// ---------------------------------------------------------------------------
extern "C" void kernel_launch(void* const* d_in, const int* in_sizes, int n_in,
                              void* d_out, int out_size) {
    const float* x    = (const float*)d_in[0];
    const float* W    = (const float*)d_in[1];
    const float* bias = (const float*)d_in[2];
    float* out = (float*)d_out;

    cudaFuncSetAttribute(gram_kernel,
                         cudaFuncAttributeMaxDynamicSharedMemorySize,
                         GRAM_SMEM_BYTES);

    xx_kernel<<<dim3(NN / 256, BB), 256>>>(x);
    transpose_kernel<<<dim3(NN / 32, CC / 32, BB), dim3(32, 8)>>>(x);
    gram_kernel<<<dim3(528, BB), 256, GRAM_SMEM_BYTES>>>(x);
    topk_kernel<<<dim3(BB * NN / 8), 256>>>();
    gather_kernel<<<dim3(NN, BB), 128>>>();
    wcat_kernel<<<OC, 256>>>(W);
    out_gemm_kernel<<<dim3(NN / 128, OC / 128, BB), 256>>>(x, bias, out);
}

// round 5
// speedup vs baseline: 1.8242x; 1.1106x over previous
#include <cuda_runtime.h>

#define BB 4
#define CC 128
#define NN 4096
#define OC 256
#define KNN 10

// Scratch (device globals — no allocation in kernel_launch)
static __device__ float g_score[(size_t)BB * NN * NN];   // 268 MB
static __device__ float g_xx[BB * NN];
static __device__ float g_xT[(size_t)BB * NN * CC];      // x transposed [b][n][c]
static __device__ float g_mT[(size_t)BB * NN * CC];      // neighbor mean [b][n][c]
static __device__ int   g_idx[BB * NN * KNN];
static __device__ float g_Wcat[OC * 2 * CC];

// ---------------------------------------------------------------------------
// K1a: per-point squared norm  xx[b][n] = sum_c x[b][c][n]^2
__global__ void xx_kernel(const float* __restrict__ x) {
    int b = blockIdx.y;
    int n = blockIdx.x * blockDim.x + threadIdx.x;
    const float* xb = x + (size_t)b * CC * NN;
    float s = 0.f;
#pragma unroll 8
    for (int c = 0; c < CC; c++) {
        float v = xb[(size_t)c * NN + n];
        s += v * v;
    }
    g_xx[b * NN + n] = s;
}

// ---------------------------------------------------------------------------
// K1b: transpose x[b][c][n] -> xT[b][n][c]
__global__ void transpose_kernel(const float* __restrict__ x) {
    __shared__ float tile[32][33];
    int b  = blockIdx.z;
    int c0 = blockIdx.y * 32;
    int n0 = blockIdx.x * 32;
    const float* xb = x + (size_t)b * CC * NN;
    int tx = threadIdx.x, ty = threadIdx.y;  // (32, 8)
#pragma unroll
    for (int r = 0; r < 32; r += 8)
        tile[ty + r][tx] = xb[(size_t)(c0 + ty + r) * NN + n0 + tx];
    __syncthreads();
#pragma unroll
    for (int r = 0; r < 32; r += 8)
        g_xT[((size_t)b * NN + n0 + ty + r) * CC + c0 + tx] = tile[tx][ty + r];
}

// ---------------------------------------------------------------------------
// K2: symmetric Gram + score epilogue (unchanged from R3 — known good).
#define GRAM_SMEM_BYTES (128 * 129 * 4)

__global__ void __launch_bounds__(256) gram_kernel(const float* __restrict__ x) {
    extern __shared__ float sm[];
    float* As = sm;              // [2][8][128]
    float* Bs = sm + 2 * 8 * 128;
    float* stage = sm;           // [128][129], reused after compute

    int b = blockIdx.y;
    int t = blockIdx.x;
    int ti = 0;
    while ((ti + 1) * 32 - (ti + 1) * ti / 2 <= t) ti++;
    int tj = ti + (t - (ti * 32 - ti * (ti - 1) / 2));
    int n0 = ti * 128, m0 = tj * 128;

    const float* xb = x + (size_t)b * CC * NN;
    int tid = threadIdx.x;
    int tx = tid % 16, ty = tid / 16;

    float acc[8][8];
#pragma unroll
    for (int i = 0; i < 8; i++)
#pragma unroll
        for (int j = 0; j < 8; j++) acc[i][j] = 0.f;

#pragma unroll
    for (int l = 0; l < 4; l++) {
        int e = tid + l * 256;
        int kk = e >> 7, col = e & 127;
        As[e] = xb[(size_t)kk * NN + n0 + col];
        Bs[e] = xb[(size_t)kk * NN + m0 + col];
    }
    __syncthreads();

    int buf = 0;
    for (int c0 = 0; c0 < CC; c0 += 8) {
        int nc = c0 + 8;
        float ra[4], rb[4];
        if (nc < CC) {
#pragma unroll
            for (int l = 0; l < 4; l++) {
                int e = tid + l * 256;
                int kk = e >> 7, col = e & 127;
                ra[l] = xb[(size_t)(nc + kk) * NN + n0 + col];
                rb[l] = xb[(size_t)(nc + kk) * NN + m0 + col];
            }
        }
#pragma unroll
        for (int kk = 0; kk < 8; kk++) {
            const float* ab = As + buf * 1024 + kk * 128;
            const float* bb = Bs + buf * 1024 + kk * 128;
            float a[8], bf[8];
            float4 a0 = *(const float4*)(ab + ty * 8);
            float4 a1 = *(const float4*)(ab + ty * 8 + 4);
            float4 b0 = *(const float4*)(bb + tx * 8);
            float4 b1 = *(const float4*)(bb + tx * 8 + 4);
            a[0]=a0.x; a[1]=a0.y; a[2]=a0.z; a[3]=a0.w;
            a[4]=a1.x; a[5]=a1.y; a[6]=a1.z; a[7]=a1.w;
            bf[0]=b0.x; bf[1]=b0.y; bf[2]=b0.z; bf[3]=b0.w;
            bf[4]=b1.x; bf[5]=b1.y; bf[6]=b1.z; bf[7]=b1.w;
#pragma unroll
            for (int i = 0; i < 8; i++)
#pragma unroll
                for (int j = 0; j < 8; j++)
                    acc[i][j] += a[i] * bf[j];
        }
        if (nc < CC) {
            int ob = buf ^ 1;
#pragma unroll
            for (int l = 0; l < 4; l++) {
                int e = tid + l * 256;
                As[ob * 1024 + e] = ra[l];
                Bs[ob * 1024 + e] = rb[l];
            }
            __syncthreads();
            buf = ob;
        }
    }

    float xxm[8];
#pragma unroll
    for (int j = 0; j < 8; j++) xxm[j] = g_xx[b * NN + m0 + tx * 8 + j];
#pragma unroll
    for (int i = 0; i < 8; i++) {
        int n = n0 + ty * 8 + i;
        float v[8];
#pragma unroll
        for (int j = 0; j < 8; j++) v[j] = 2.f * acc[i][j] - xxm[j];
        float* row = g_score + ((size_t)b * NN + n) * NN + m0 + tx * 8;
        ((float4*)row)[0] = make_float4(v[0], v[1], v[2], v[3]);
        ((float4*)row)[1] = make_float4(v[4], v[5], v[6], v[7]);
    }

    if (ti != tj) {
        __syncthreads();
        float xxn[8];
#pragma unroll
        for (int i = 0; i < 8; i++) xxn[i] = g_xx[b * NN + n0 + ty * 8 + i];
#pragma unroll
        for (int i = 0; i < 8; i++)
#pragma unroll
            for (int j = 0; j < 8; j++)
                stage[(tx * 8 + j) * 129 + ty * 8 + i] = 2.f * acc[i][j] - xxn[i];
        __syncthreads();
        int r  = tid >> 1;
        int ch = (tid & 1) * 64;
        float* row = g_score + ((size_t)b * NN + m0 + r) * NN + n0 + ch;
        const float* srow = stage + r * 129 + ch;
#pragma unroll
        for (int q = 0; q < 16; q++) {
            ((float4*)row)[q] = make_float4(srow[q * 4 + 0], srow[q * 4 + 1],
                                            srow[q * 4 + 2], srow[q * 4 + 3]);
        }
    }
}

// ---------------------------------------------------------------------------
// K3: top-K per row, one warp per row.
// All 32 lanes keep an IDENTICAL (replicated) sorted top-10 in registers.
// Fast path: fmax-tree + 1 compare vs warp-global 10th-best + 1 ballot.
// Candidates broadcast via shfl and inserted coherently by all lanes.
// Threshold re-checked inside the pop loop kills stale candidates.
// Insertion chain is always-exact; threshold is purely a perf filter.
// Tie-break: value desc, index asc (matches jax.lax.top_k).
__global__ void __launch_bounds__(256) topk_kernel() {
    const unsigned FULL = 0xffffffffu;
    int gw   = (blockIdx.x * 256 + threadIdx.x) >> 5;  // global row
    int lane = threadIdx.x & 31;
    int b = gw >> 12;        // / NN
    int n = gw & (NN - 1);
    const float4* row = (const float4*)(g_score + ((size_t)b * NN + n) * NN);

    const float NEG = -3.4028235e38f;
    float lv[KNN];
    int   li[KNN];
#pragma unroll
    for (int k = 0; k < KNN; k++) { lv[k] = NEG; li[k] = 0x7fffffff; }
    float thr = NEG;
    int   tix = 0x7fffffff;

    float4 cur = row[lane];
    for (int j = 0; j < NN / 4 / 32; j++) {  // 32 iterations
        float4 nxt;
        if (j < NN / 4 / 32 - 1) nxt = row[(j + 1) * 32 + lane];
        int base = (j * 32 + lane) * 4;
        float m4 = fmaxf(fmaxf(cur.x, cur.y), fmaxf(cur.z, cur.w));
        if (__ballot_sync(FULL, m4 >= thr)) {
            float ev0 = cur.x, ev1 = cur.y, ev2 = cur.z, ev3 = cur.w;
#pragma unroll
            for (int e = 0; e < 4; e++) {
                float v = (e == 0) ? ev0 : (e == 1) ? ev1 : (e == 2) ? ev2 : ev3;
                int idx = base + e;
                bool cand = (v > thr) || (v == thr && idx < tix);
                unsigned m = __ballot_sync(FULL, cand);
                while (m) {
                    int src = __ffs(m) - 1;
                    float bv = __shfl_sync(FULL, v, src);
                    int   bi = __shfl_sync(FULL, idx, src);
                    // coherent insert into replicated sorted list
                    float cv = bv; int ci = bi;
#pragma unroll
                    for (int k = 0; k < KNN; k++) {
                        bool sw = (cv > lv[k]) || (cv == lv[k] && ci < li[k]);
                        float tv = sw ? lv[k] : cv;
                        int   tq = sw ? li[k] : ci;
                        lv[k] = sw ? cv : lv[k];
                        li[k] = sw ? ci : li[k];
                        cv = tv; ci = tq;
                    }
                    thr = lv[KNN - 1]; tix = li[KNN - 1];
                    if (lane == src) cand = false;
                    cand = cand && ((v > thr) || (v == thr && idx < tix));
                    m = __ballot_sync(FULL, cand);
                }
            }
        }
        cur = nxt;
    }

#pragma unroll
    for (int k = 0; k < KNN; k++)
        if (lane == k) g_idx[(b * NN + n) * KNN + k] = li[k];
}

// ---------------------------------------------------------------------------
// K4: neighbor mean  mT[b][n][c] = (1/K) sum_k xT[b][idx_k][c]
__global__ void gather_kernel() {
    int b = blockIdx.y;
    int n = blockIdx.x;
    int c = threadIdx.x;  // 128
    __shared__ int sidx[KNN];
    if (c < KNN) sidx[c] = g_idx[(b * NN + n) * KNN + c];
    __syncthreads();
    float acc = 0.f;
#pragma unroll
    for (int k = 0; k < KNN; k++)
        acc += g_xT[((size_t)b * NN + sidx[k]) * CC + c];
    g_mT[((size_t)b * NN + n) * CC + c] = acc / (float)KNN;
}

// ---------------------------------------------------------------------------
// K5: Wcat[o][c] = W1 for c<128, (W2 - W1) for c>=128
__global__ void wcat_kernel(const float* __restrict__ W) {
    int idx = blockIdx.x * 256 + threadIdx.x;
    int c = idx % (2 * CC);
    float v = W[idx];
    if (c >= CC) v -= W[idx - CC];
    g_Wcat[idx] = v;
}

// ---------------------------------------------------------------------------
// K6: out[b][o][n] = sum_c Wcat[o][c] * cat[c][n] + bias[o]
//     cat[0:128][n] = mT[b][n][c],  cat[128:256][n] = x[b][c][n]
//     Double-buffered like gram_kernel.
__global__ void __launch_bounds__(256) out_gemm_kernel(
    const float* __restrict__ x, const float* __restrict__ bias,
    float* __restrict__ out) {
    __shared__ float As[2][1024];
    __shared__ float Bs[2][1024];

    int b  = blockIdx.z;
    int o0 = blockIdx.y * 128;
    int n0 = blockIdx.x * 128;
    const float* xb = x + (size_t)b * CC * NN;

    int tid = threadIdx.x;
    int tx = tid % 16, ty = tid / 16;

    float acc[8][8];
#pragma unroll
    for (int i = 0; i < 8; i++)
#pragma unroll
        for (int j = 0; j < 8; j++) acc[i][j] = 0.f;

    // load stage c0 into registers
    auto load_stage = [&](int c0, float* ra, float* rb) {
#pragma unroll
        for (int l = 0; l < 4; l++) {
            int e  = tid + l * 256;
            int kk = e % 8;
            int i  = e / 8;
            ra[l] = g_Wcat[(o0 + i) * (2 * CC) + c0 + kk];
        }
        if (c0 < CC) {
#pragma unroll
            for (int l = 0; l < 4; l++) {
                int e  = tid + l * 256;
                int kk = e % 8;
                int j  = e / 8;
                rb[l] = g_mT[((size_t)b * NN + n0 + j) * CC + c0 + kk];
            }
        } else {
#pragma unroll
            for (int l = 0; l < 4; l++) {
                int e  = tid + l * 256;
                int kk = e / 128;
                int j  = e % 128;
                rb[l] = xb[(size_t)(c0 - CC + kk) * NN + n0 + j];
            }
        }
    };
    auto commit = [&](int buf, const float* ra, const float* rb) {
#pragma unroll
        for (int l = 0; l < 4; l++) {
            int e = tid + l * 256;
            As[buf][(e % 8) * 128 + e / 8] = ra[l];
            if ((e % 8) * 128 + e / 8 >= 0) {}  // no-op
        }
#pragma unroll
        for (int l = 0; l < 4; l++) {
            int e = tid + l * 256;
            int kk, j;
            if (true) { kk = e % 8; j = e / 8; }
            Bs[buf][kk * 128 + j] = rb[l];
        }
    };

    {
        float ra[4], rb[4];
        load_stage(0, ra, rb);
        // As layout [kk][i], Bs layout [kk][j]
#pragma unroll
        for (int l = 0; l < 4; l++) {
            int e = tid + l * 256;
            As[0][(e % 8) * 128 + e / 8] = ra[l];
        }
#pragma unroll
        for (int l = 0; l < 4; l++) {
            int e = tid + l * 256;
            Bs[0][(e % 8) * 128 + e / 8] = rb[l];
        }
        __syncthreads();
    }

    int buf = 0;
    for (int c0 = 0; c0 < 2 * CC; c0 += 8) {
        int nc = c0 + 8;
        float ra[4], rb[4];
        bool rb_xlayout = false;
        if (nc < 2 * CC) {
#pragma unroll
            for (int l = 0; l < 4; l++) {
                int e  = tid + l * 256;
                int kk = e % 8;
                int i  = e / 8;
                ra[l] = g_Wcat[(o0 + i) * (2 * CC) + nc + kk];
            }
            if (nc < CC) {
#pragma unroll
                for (int l = 0; l < 4; l++) {
                    int e  = tid + l * 256;
                    int kk = e % 8;
                    int j  = e / 8;
                    rb[l] = g_mT[((size_t)b * NN + n0 + j) * CC + nc + kk];
                }
            } else {
                rb_xlayout = true;
#pragma unroll
                for (int l = 0; l < 4; l++) {
                    int e  = tid + l * 256;
                    int kk = e / 128;
                    int j  = e % 128;
                    rb[l] = xb[(size_t)(nc - CC + kk) * NN + n0 + j];
                }
            }
        }
#pragma unroll
        for (int kk = 0; kk < 8; kk++) {
            const float* ab = As[buf] + kk * 128;
            const float* bb = Bs[buf] + kk * 128;
            float a[8], bf[8];
            float4 a0 = *(const float4*)(ab + ty * 8);
            float4 a1 = *(const float4*)(ab + ty * 8 + 4);
            float4 b0 = *(const float4*)(bb + tx * 8);
            float4 b1 = *(const float4*)(bb + tx * 8 + 4);
            a[0]=a0.x; a[1]=a0.y; a[2]=a0.z; a[3]=a0.w;
            a[4]=a1.x; a[5]=a1.y; a[6]=a1.z; a[7]=a1.w;
            bf[0]=b0.x; bf[1]=b0.y; bf[2]=b0.z; bf[3]=b0.w;
            bf[4]=b1.x; bf[5]=b1.y; bf[6]=b1.z; bf[7]=b1.w;
#pragma unroll
            for (int i = 0; i < 8; i++)
#pragma unroll
                for (int j = 0; j < 8; j++)
                    acc[i][j] += a[i] * bf[j];
        }
        if (nc < 2 * CC) {
            int ob = buf ^ 1;
#pragma unroll
            for (int l = 0; l < 4; l++) {
                int e = tid + l * 256;
                As[ob][(e % 8) * 128 + e / 8] = ra[l];
            }
            if (!rb_xlayout) {
#pragma unroll
                for (int l = 0; l < 4; l++) {
                    int e = tid + l * 256;
                    Bs[ob][(e % 8) * 128 + e / 8] = rb[l];
                }
            } else {
#pragma unroll
                for (int l = 0; l < 4; l++) {
                    int e = tid + l * 256;
                    Bs[ob][(e / 128) * 128 + (e % 128)] = rb[l];
                }
            }
            __syncthreads();
            buf = ob;
        }
    }

#pragma unroll
    for (int i = 0; i < 8; i++) {
        int o = o0 + ty * 8 + i;
        float bv = bias[o];
        float* orow = out + ((size_t)(b * OC + o)) * NN + n0 + tx * 8;
        float v[8];
#pragma unroll
        for (int j = 0; j < 8; j++) v[j] = acc[i][j] + bv;
        ((float4*)orow)[0] = make_float4(v[0], v[1], v[2], v[3]);
        ((float4*)orow)[1] = make_float4(v[4], v[5], v[6], v[7]);
    }
}

// ---------------------------------------------------------------------------
extern "C" void kernel_launch(void* const* d_in, const int* in_sizes, int n_in,
                              void* d_out, int out_size) {
    const float* x    = (const float*)d_in[0];
    const float* W    = (const float*)d_in[1];
    const float* bias = (const float*)d_in[2];
    float* out = (float*)d_out;

    cudaFuncSetAttribute(gram_kernel,
                         cudaFuncAttributeMaxDynamicSharedMemorySize,
                         GRAM_SMEM_BYTES);

    xx_kernel<<<dim3(NN / 256, BB), 256>>>(x);
    transpose_kernel<<<dim3(NN / 32, CC / 32, BB), dim3(32, 8)>>>(x);
    gram_kernel<<<dim3(528, BB), 256, GRAM_SMEM_BYTES>>>(x);
    topk_kernel<<<dim3(BB * NN / 8), 256>>>();
    gather_kernel<<<dim3(NN, BB), 128>>>();
    wcat_kernel<<<OC, 256>>>(W);
    out_gemm_kernel<<<dim3(NN / 128, OC / 128, BB), 256>>>(x, bias, out);
}